// round 5
// baseline (speedup 1.0000x reference)
#include <cuda_runtime.h>

#define LRES 1024
#define TOPK 48
#define EF   416
#define SF   1280
#define KT   16
#define NTILE 3

#define OFF_E       0ull
#define OFF_EIDX    6291456ull
#define OFF_ES      6340608ull
#define OFF_EIDXSUB 12632064ull

__device__ float g_coords[LRES * 15];
__device__ int   g_eidx[LRES * TOPK];
__device__ float g_dnb[LRES * TOPK];

__device__ __forceinline__ unsigned long long u64min_(unsigned long long a,
                                                      unsigned long long b) {
    return a < b ? a : b;
}

__device__ __forceinline__ unsigned long long fma2(unsigned long long a,
                                                   unsigned long long b,
                                                   unsigned long long c) {
    unsigned long long d;
    asm("fma.rn.f32x2 %0, %1, %2, %3;" : "=l"(d) : "l"(a), "l"(b), "l"(c));
    return d;
}

__device__ __forceinline__ float pairsum(unsigned long long v) {
    float lo, hi;
    asm("mov.b64 {%0, %1}, %2;" : "=f"(lo), "=f"(hi) : "l"(v));
    return lo + hi;
}

// Chained RBF: rbf_r(D) = exp(-((D-2)/sig - r*dl)^2), r = 0..NB-1,
// where s=(D-2)*SINV is the bin coordinate, D2 = dl^2*... (delta^2),
// computed with 2 MUFU via running products; guarded reverse chain for
// the rare case where rbf_0 underflows while upper bins don't.
template <int NB>
__device__ __forceinline__ void rbf_gen(float D, float m, float* __restrict__ fr,
                                        float SINV, float D2, float E2c) {
    float s = (D - 2.0f) * SINV;
    float v = __expf(-D2 * s * s);
    float g = __expf(D2 * (2.0f * s - 1.0f));
    float vals[NB];
    vals[0] = v;
    #pragma unroll
    for (int r = 1; r < NB; r++) { v *= g; g *= E2c; vals[r] = v; }
    if (vals[0] < 1e-30f) {
        float sN = s - (float)(NB - 1);
        float v1 = __expf(-D2 * sN * sN);
        float g1 = __expf(-D2 * (2.0f * sN + 1.0f));
        vals[NB - 1] = fmaxf(vals[NB - 1], v1);
        #pragma unroll
        for (int r = NB - 2; r >= 0; r--) {
            v1 *= g1; g1 *= E2c;
            vals[r] = fmaxf(vals[r], v1);
        }
    }
    #pragma unroll
    for (int r = 0; r < NB; r++) fr[r] = m * vals[r];
}

// e: 16 bins, sigma=1.25, step=4/3:  SINV=0.75, D2=(16/15)^2, E2=e^{-2*D2}
#define E_SINV 0.75f
#define E_D2   1.13777778f
#define E_E2   0.10273980f
// es: 8 bins, sigma=2.5, step=20/7:  SINV=0.35, D2=(8/7)^2, E2=e^{-2*D2}
#define S_SINV 0.35f
#define S_D2   1.30612245f
#define S_E2   0.07336966f

// Stage a 128ch x 32feat W tile into smem, row pitch 36 floats.
__device__ __forceinline__ void stage_w(const float* __restrict__ W, int stride,
                                        int f0, float* __restrict__ Wsm,
                                        int tid) {
    #pragma unroll
    for (int p = tid; p < 1024; p += 256) {
        int o = p >> 3, j = (p & 7) << 2;
        float4 w = *(const float4*)(W + (size_t)o * stride + f0 + j);
        *(float4*)(Wsm + o * 36 + j) = w;
    }
}

// ---------------------------------------------------------------------------
__global__ void geom_kernel(const float* __restrict__ X) {
    int i = blockIdx.x * blockDim.x + threadIdx.x;
    if (i >= LRES) return;
    const float* xi = X + (size_t)i * 37 * 3;
    float n0 = xi[0],  n1 = xi[1],  n2 = xi[2];
    float a0 = xi[3],  a1 = xi[4],  a2 = xi[5];
    float c0 = xi[6],  c1 = xi[7],  c2 = xi[8];
    float o0 = xi[12], o1 = xi[13], o2 = xi[14];
    float b0 = a0 - n0, b1 = a1 - n1, b2 = a2 - n2;
    float d0 = c0 - a0, d1 = c1 - a1, d2 = c2 - a2;
    float x0 = b1 * d2 - b2 * d1;
    float x1 = b2 * d0 - b0 * d2;
    float x2 = b0 * d1 - b1 * d0;
    float cb0 = -0.58273431f * x0 + 0.56802827f * b0 - 0.54067466f * d0 + a0;
    float cb1 = -0.58273431f * x1 + 0.56802827f * b1 - 0.54067466f * d1 + a1;
    float cb2 = -0.58273431f * x2 + 0.56802827f * b2 - 0.54067466f * d2 + a2;
    float* dst = g_coords + i * 15;
    dst[0] = n0;  dst[1] = n1;  dst[2] = n2;
    dst[3] = a0;  dst[4] = a1;  dst[5] = a2;
    dst[6] = c0;  dst[7] = c1;  dst[8] = c2;
    dst[9] = o0;  dst[10] = o1; dst[11] = o2;
    dst[12] = cb0; dst[13] = cb1; dst[14] = cb2;
}

// ---------------------------------------------------------------------------
__global__ void topk_kernel(const float* __restrict__ X,
                            const float* __restrict__ mask,
                            float* __restrict__ out) {
    __shared__ float dsh[LRES];
    __shared__ unsigned long long keys[LRES];
    __shared__ float wmaxs[8];
    __shared__ unsigned long long wmins[8];
    __shared__ float smDmax;

    int i = blockIdx.x;
    int tid = threadIdx.x;
    float cax = X[((size_t)i * 37 + 1) * 3 + 0];
    float cay = X[((size_t)i * 37 + 1) * 3 + 1];
    float caz = X[((size_t)i * 37 + 1) * 3 + 2];
    float mi = mask[i];

    float lmax = 0.0f;
    for (int j = tid; j < LRES; j += 256) {
        float dx = cax - X[((size_t)j * 37 + 1) * 3 + 0];
        float dy = cay - X[((size_t)j * 37 + 1) * 3 + 1];
        float dz = caz - X[((size_t)j * 37 + 1) * 3 + 2];
        float s = dx * dx + dy * dy + dz * dz;
        float m2 = mi * mask[j];
        float Dv = m2 * sqrtf(s + 1e-6f);
        dsh[j] = Dv;
        lmax = fmaxf(lmax, Dv);
    }
    for (int off = 16; off; off >>= 1)
        lmax = fmaxf(lmax, __shfl_xor_sync(0xffffffffu, lmax, off));
    if ((tid & 31) == 0) wmaxs[tid >> 5] = lmax;
    __syncthreads();
    if (tid == 0) {
        float m = wmaxs[0];
        #pragma unroll
        for (int w = 1; w < 8; w++) m = fmaxf(m, wmaxs[w]);
        smDmax = m;
    }
    __syncthreads();
    float Dmax = smDmax;

    for (int j = tid; j < LRES; j += 256) {
        float m2 = mi * mask[j];
        float Dadj = dsh[j] + (1.0f - m2) * Dmax;
        keys[j] = (((unsigned long long)__float_as_uint(Dadj)) << 32) |
                  (unsigned int)j;
    }
    __syncthreads();

    for (int sel = 0; sel < TOPK; sel++) {
        unsigned long long lmin = 0xffffffffffffffffull;
        #pragma unroll
        for (int c = 0; c < 4; c++) lmin = u64min_(lmin, keys[tid + 256 * c]);
        for (int off = 16; off; off >>= 1) {
            unsigned long long o2 = __shfl_xor_sync(0xffffffffu, lmin, off);
            lmin = u64min_(lmin, o2);
        }
        if ((tid & 31) == 0) wmins[tid >> 5] = lmin;
        __syncthreads();
        if (tid == 0) {
            unsigned long long m = wmins[0];
            #pragma unroll
            for (int w = 1; w < 8; w++) m = u64min_(m, wmins[w]);
            int j = (int)(m & 0xffffffffull);
            float dv = __uint_as_float((unsigned int)(m >> 32));
            g_eidx[i * TOPK + sel] = j;
            g_dnb[i * TOPK + sel] = dv;
            out[OFF_EIDX + (size_t)i * TOPK + sel] = (float)j;
            out[OFF_EIDXSUB + (size_t)i * TOPK + sel] = (float)j;
            keys[j] = 0xffffffffffffffffull;
        }
        __syncthreads();
    }
}

// ---------------------------------------------------------------------------
// Kernel 3: E. 256 threads; thread tile = 12 edges x 2 channels.
// eg = tid&3 (4 groups of 12 edges), cp = tid>>2 (64 channel pairs).
// ---------------------------------------------------------------------------
__global__ void __launch_bounds__(256) e_kernel(
    const float* __restrict__ Wpos, const float* __restrict__ bpos,
    const int* __restrict__ ridx, const int* __restrict__ clab,
    const float* __restrict__ We, const float* __restrict__ ge,
    const float* __restrict__ be, float* __restrict__ out) {
    extern __shared__ float feats[];  // 48*416 floats, then Wsm 128*36
    float* Wsm = feats + TOPK * EF;
    int i = blockIdx.x;
    int tid = threadIdx.x;

    if (tid < TOPK) {
        int k = tid;
        int j = g_eidx[i * TOPK + k];
        int offr = ridx[i] - ridx[j];
        int ec = (clab[i] == clab[j]) ? 1 : 0;
        int d = min(max(offr + 32, 0), 64) * ec + (1 - ec) * 65;
        float* fr = feats + k * EF;
        #pragma unroll
        for (int f = 0; f < 16; f++) fr[f] = Wpos[f * 66 + d] + bpos[f];
        rbf_gen<16>(g_dnb[i * TOPK + k], 1.0f, fr + 16, E_SINV, E_D2, E_E2);
    }

    const signed char pa[24] = {0,2,3,4,1,1,1,1,0,0,0,4,4,3,0,2,3,4,2,3,4,2,3,2};
    const signed char pb[24] = {0,2,3,4,0,2,3,4,2,3,4,2,3,2,1,1,1,1,0,0,0,4,4,3};
    for (int tt = tid; tt < TOPK * 24; tt += 256) {
        int k = tt / 24, p = tt - k * 24;
        int j = g_eidx[i * TOPK + k];
        const float* A = g_coords + i * 15 + (int)pa[p] * 3;
        const float* B = g_coords + j * 15 + (int)pb[p] * 3;
        float dx = A[0] - B[0], dy = A[1] - B[1], dz = A[2] - B[2];
        float D = sqrtf(dx * dx + dy * dy + dz * dz + 1e-6f);
        rbf_gen<16>(D, 1.0f, feats + k * EF + 32 + p * 16, E_SINV, E_D2, E_E2);
    }

    int eg = tid & 3;
    int cp = tid >> 2;
    int o0 = 2 * cp, o1 = 2 * cp + 1;
    unsigned long long acc0[12], acc1[12];
    #pragma unroll
    for (int k = 0; k < 12; k++) { acc0[k] = 0ull; acc1[k] = 0ull; }

    for (int st = 0; st < EF / 32; st++) {
        __syncthreads();
        stage_w(We, EF, st * 32, Wsm, tid);
        __syncthreads();
        int f0 = st * 32;
        #pragma unroll
        for (int q = 0; q < 8; q++) {
            ulonglong2 w0 = *(const ulonglong2*)(Wsm + o0 * 36 + 4 * q);
            ulonglong2 w1 = *(const ulonglong2*)(Wsm + o1 * 36 + 4 * q);
            #pragma unroll
            for (int k = 0; k < 12; k++) {
                ulonglong2 v = *(const ulonglong2*)(feats +
                                   (eg * 12 + k) * EF + f0 + 4 * q);
                acc0[k] = fma2(w0.x, v.x, acc0[k]);
                acc0[k] = fma2(w0.y, v.y, acc0[k]);
                acc1[k] = fma2(w1.x, v.x, acc1[k]);
                acc1[k] = fma2(w1.y, v.y, acc1[k]);
            }
        }
    }
    __syncthreads();

    float* h = feats;  // 48*128
    #pragma unroll
    for (int k = 0; k < 12; k++) {
        h[(eg * 12 + k) * 128 + o0] = pairsum(acc0[k]);
        h[(eg * 12 + k) * 128 + o1] = pairsum(acc1[k]);
    }
    __syncthreads();

    int wid = tid >> 5, lane = tid & 31;
    for (int k = wid; k < TOPK; k += 8) {
        float v0 = h[k * 128 + lane];
        float v1 = h[k * 128 + lane + 32];
        float v2 = h[k * 128 + lane + 64];
        float v3 = h[k * 128 + lane + 96];
        float s = v0 + v1 + v2 + v3;
        for (int off = 16; off; off >>= 1) s += __shfl_xor_sync(0xffffffffu, s, off);
        float mu = s * (1.0f / 128.0f);
        float d0 = v0 - mu, d1 = v1 - mu, d2 = v2 - mu, d3 = v3 - mu;
        float s2 = d0 * d0 + d1 * d1 + d2 * d2 + d3 * d3;
        for (int off = 16; off; off >>= 1) s2 += __shfl_xor_sync(0xffffffffu, s2, off);
        float inv = rsqrtf(s2 * (1.0f / 128.0f) + 1e-5f);
        size_t base = OFF_E + ((size_t)(i * TOPK + k)) * 128;
        out[base + lane]      = ge[lane]      * d0 * inv + be[lane];
        out[base + lane + 32] = ge[lane + 32] * d1 * inv + be[lane + 32];
        out[base + lane + 64] = ge[lane + 64] * d2 * inv + be[lane + 64];
        out[base + lane + 96] = ge[lane + 96] * d3 * inv + be[lane + 96];
    }
}

// ---------------------------------------------------------------------------
// Kernel 4: E_s. 256 threads; thread tile = 4 edges x 2 channels.
// ---------------------------------------------------------------------------
__global__ void __launch_bounds__(256) es_kernel(
    const float* __restrict__ X, const float* __restrict__ amask,
    const float* __restrict__ Ws, const float* __restrict__ gs,
    const float* __restrict__ bs, float* __restrict__ out) {
    extern __shared__ float feats[];  // 16*1280 floats, then Wsm 128*36
    float* Wsm = feats + KT * SF;
    __shared__ int jn[KT];
    __shared__ float anch[15];

    int bx = blockIdx.x;
    int i = bx / NTILE;
    int k0 = (bx - i * NTILE) * KT;
    int tid = threadIdx.x;

    if (tid < KT) jn[tid] = g_eidx[i * TOPK + k0 + tid];
    if (tid >= 32 && tid < 47) anch[tid - 32] = g_coords[i * 15 + (tid - 32)];
    __syncthreads();

    for (int tt = tid; tt < KT * 160; tt += 256) {
        int kk = tt / 160;
        int rem = tt - kk * 160;
        int a = rem >> 5, s = rem & 31;
        int j = jn[kk];
        const float* Sp = X + ((size_t)j * 37 + 5 + s) * 3;
        float dx = anch[a * 3 + 0] - Sp[0];
        float dy = anch[a * 3 + 1] - Sp[1];
        float dz = anch[a * 3 + 2] - Sp[2];
        float D = sqrtf(dx * dx + dy * dy + dz * dz + 1e-6f);
        float m = amask[(size_t)j * 37 + 5 + s];
        rbf_gen<8>(D, m, feats + kk * SF + (a * 32 + s) * 8, S_SINV, S_D2, S_E2);
    }

    int eg = tid & 3;
    int cp = tid >> 2;
    int o0 = 2 * cp, o1 = 2 * cp + 1;
    unsigned long long acc0[4], acc1[4];
    #pragma unroll
    for (int k = 0; k < 4; k++) { acc0[k] = 0ull; acc1[k] = 0ull; }

    for (int st = 0; st < SF / 32; st++) {
        __syncthreads();
        stage_w(Ws, SF, st * 32, Wsm, tid);
        __syncthreads();
        int f0 = st * 32;
        #pragma unroll
        for (int q = 0; q < 8; q++) {
            ulonglong2 w0 = *(const ulonglong2*)(Wsm + o0 * 36 + 4 * q);
            ulonglong2 w1 = *(const ulonglong2*)(Wsm + o1 * 36 + 4 * q);
            #pragma unroll
            for (int k = 0; k < 4; k++) {
                ulonglong2 v = *(const ulonglong2*)(feats +
                                   (eg * 4 + k) * SF + f0 + 4 * q);
                acc0[k] = fma2(w0.x, v.x, acc0[k]);
                acc0[k] = fma2(w0.y, v.y, acc0[k]);
                acc1[k] = fma2(w1.x, v.x, acc1[k]);
                acc1[k] = fma2(w1.y, v.y, acc1[k]);
            }
        }
    }
    __syncthreads();

    float* h = feats;  // 16*128
    #pragma unroll
    for (int k = 0; k < 4; k++) {
        h[(eg * 4 + k) * 128 + o0] = pairsum(acc0[k]);
        h[(eg * 4 + k) * 128 + o1] = pairsum(acc1[k]);
    }
    __syncthreads();

    int wid = tid >> 5, lane = tid & 31;
    for (int kk = wid; kk < KT; kk += 8) {
        float v0 = h[kk * 128 + lane];
        float v1 = h[kk * 128 + lane + 32];
        float v2 = h[kk * 128 + lane + 64];
        float v3 = h[kk * 128 + lane + 96];
        float s = v0 + v1 + v2 + v3;
        for (int off = 16; off; off >>= 1) s += __shfl_xor_sync(0xffffffffu, s, off);
        float mu = s * (1.0f / 128.0f);
        float d0 = v0 - mu, d1 = v1 - mu, d2 = v2 - mu, d3 = v3 - mu;
        float s2 = d0 * d0 + d1 * d1 + d2 * d2 + d3 * d3;
        for (int off = 16; off; off >>= 1) s2 += __shfl_xor_sync(0xffffffffu, s2, off);
        float inv = rsqrtf(s2 * (1.0f / 128.0f) + 1e-5f);
        size_t base = OFF_ES + ((size_t)(i * TOPK + k0 + kk)) * 128;
        out[base + lane]      = gs[lane]      * d0 * inv + bs[lane];
        out[base + lane + 32] = gs[lane + 32] * d1 * inv + bs[lane + 32];
        out[base + lane + 64] = gs[lane + 64] * d2 * inv + bs[lane + 64];
        out[base + lane + 96] = gs[lane + 96] * d3 * inv + bs[lane + 96];
    }
}

// ---------------------------------------------------------------------------
extern "C" void kernel_launch(void* const* d_in, const int* in_sizes, int n_in,
                              void* d_out, int out_size) {
    (void)in_sizes; (void)n_in; (void)out_size;
    const float* X     = (const float*)d_in[0];
    const float* mask  = (const float*)d_in[2];
    const float* amask = (const float*)d_in[3];
    const int*   ridx  = (const int*)d_in[4];
    const int*   clab  = (const int*)d_in[6];
    const float* Wpos  = (const float*)d_in[7];
    const float* bpos  = (const float*)d_in[8];
    const float* We    = (const float*)d_in[9];
    const float* ge    = (const float*)d_in[10];
    const float* be    = (const float*)d_in[11];
    const float* Ws    = (const float*)d_in[12];
    const float* gs    = (const float*)d_in[13];
    const float* bs    = (const float*)d_in[14];
    float* out = (float*)d_out;

    int e_smem  = TOPK * EF * 4 + 128 * 36 * 4;   // 79872 + 18432 = 98304
    int es_smem = KT * SF * 4 + 128 * 36 * 4;     // 81920 + 18432 = 100352
    cudaFuncSetAttribute(e_kernel, cudaFuncAttributeMaxDynamicSharedMemorySize,
                         e_smem);
    cudaFuncSetAttribute(es_kernel, cudaFuncAttributeMaxDynamicSharedMemorySize,
                         es_smem);

    geom_kernel<<<(LRES + 255) / 256, 256>>>(X);
    topk_kernel<<<LRES, 256>>>(X, mask, out);
    e_kernel<<<LRES, 256, e_smem>>>(Wpos, bpos, ridx, clab, We, ge, be, out);
    es_kernel<<<LRES * NTILE, 256, es_smem>>>(X, amask, Ws, gs, bs, out);
}

// round 6
// speedup vs baseline: 3.4656x; 3.4656x over previous
#include <cuda_runtime.h>

#define LRES 1024
#define TOPK 48
#define EF   416
#define SF   1280
#define KT   16
#define NTILE 3

#define OFF_E       0ull
#define OFF_EIDX    6291456ull
#define OFF_ES      6340608ull
#define OFF_EIDXSUB 12632064ull

__device__ float g_coords[LRES * 15];
__device__ int   g_eidx[LRES * TOPK];
__device__ float g_dnb[LRES * TOPK];

__device__ __forceinline__ unsigned long long u64min_(unsigned long long a,
                                                      unsigned long long b) {
    return a < b ? a : b;
}

__device__ __forceinline__ unsigned long long fma2(unsigned long long a,
                                                   unsigned long long b,
                                                   unsigned long long c) {
    unsigned long long d;
    asm("fma.rn.f32x2 %0, %1, %2, %3;" : "=l"(d) : "l"(a), "l"(b), "l"(c));
    return d;
}

__device__ __forceinline__ float pairsum(unsigned long long v) {
    float lo, hi;
    asm("mov.b64 {%0, %1}, %2;" : "=f"(lo), "=f"(hi) : "l"(v));
    return lo + hi;
}

// Chained RBF (2 expf instead of NB expf), guarded reverse chain vs underflow.
template <int NB>
__device__ __forceinline__ void rbf_gen(float D, float m, float* __restrict__ fr,
                                        float SINV, float D2, float E2c) {
    float s = (D - 2.0f) * SINV;
    float v = __expf(-D2 * s * s);
    float g = __expf(D2 * (2.0f * s - 1.0f));
    float vals[NB];
    vals[0] = v;
    #pragma unroll
    for (int r = 1; r < NB; r++) { v *= g; g *= E2c; vals[r] = v; }
    if (vals[0] < 1e-30f) {
        float sN = s - (float)(NB - 1);
        float v1 = __expf(-D2 * sN * sN);
        float g1 = __expf(-D2 * (2.0f * sN + 1.0f));
        vals[NB - 1] = fmaxf(vals[NB - 1], v1);
        #pragma unroll
        for (int r = NB - 2; r >= 0; r--) {
            v1 *= g1; g1 *= E2c;
            vals[r] = fmaxf(vals[r], v1);
        }
    }
    #pragma unroll
    for (int r = 0; r < NB; r++) fr[r] = m * vals[r];
}

#define E_SINV 0.75f
#define E_D2   1.13777778f
#define E_E2   0.10273980f
#define S_SINV 0.35f
#define S_D2   1.30612245f
#define S_E2   0.07336966f

// Stage 128ch x 32feat tile into Wsm2[f2*130 + ch] (ull = packed (2f2,2f2+1)).
__device__ __forceinline__ void stage_w(const float* __restrict__ W, int stride,
                                        int f0, unsigned long long* Wsm2,
                                        int tid) {
    #pragma unroll
    for (int p = tid; p < 2048; p += 256) {
        int o = p >> 4, f2 = p & 15;
        float2 v = *(const float2*)(W + (size_t)o * stride + f0 + 2 * f2);
        unsigned long long u;
        asm("mov.b64 %0, {%1, %2};" : "=l"(u) : "f"(v.x), "f"(v.y));
        Wsm2[f2 * 130 + o] = u;
    }
}

// ---------------------------------------------------------------------------
__global__ void geom_kernel(const float* __restrict__ X) {
    int i = blockIdx.x * blockDim.x + threadIdx.x;
    if (i >= LRES) return;
    const float* xi = X + (size_t)i * 37 * 3;
    float n0 = xi[0],  n1 = xi[1],  n2 = xi[2];
    float a0 = xi[3],  a1 = xi[4],  a2 = xi[5];
    float c0 = xi[6],  c1 = xi[7],  c2 = xi[8];
    float o0 = xi[12], o1 = xi[13], o2 = xi[14];
    float b0 = a0 - n0, b1 = a1 - n1, b2 = a2 - n2;
    float d0 = c0 - a0, d1 = c1 - a1, d2 = c2 - a2;
    float x0 = b1 * d2 - b2 * d1;
    float x1 = b2 * d0 - b0 * d2;
    float x2 = b0 * d1 - b1 * d0;
    float cb0 = -0.58273431f * x0 + 0.56802827f * b0 - 0.54067466f * d0 + a0;
    float cb1 = -0.58273431f * x1 + 0.56802827f * b1 - 0.54067466f * d1 + a1;
    float cb2 = -0.58273431f * x2 + 0.56802827f * b2 - 0.54067466f * d2 + a2;
    float* dst = g_coords + i * 15;
    dst[0] = n0;  dst[1] = n1;  dst[2] = n2;
    dst[3] = a0;  dst[4] = a1;  dst[5] = a2;
    dst[6] = c0;  dst[7] = c1;  dst[8] = c2;
    dst[9] = o0;  dst[10] = o1; dst[11] = o2;
    dst[12] = cb0; dst[13] = cb1; dst[14] = cb2;
}

// ---------------------------------------------------------------------------
__global__ void topk_kernel(const float* __restrict__ X,
                            const float* __restrict__ mask,
                            float* __restrict__ out) {
    __shared__ float dsh[LRES];
    __shared__ unsigned long long keys[LRES];
    __shared__ float wmaxs[8];
    __shared__ unsigned long long wmins[8];
    __shared__ float smDmax;

    int i = blockIdx.x;
    int tid = threadIdx.x;
    float cax = X[((size_t)i * 37 + 1) * 3 + 0];
    float cay = X[((size_t)i * 37 + 1) * 3 + 1];
    float caz = X[((size_t)i * 37 + 1) * 3 + 2];
    float mi = mask[i];

    float lmax = 0.0f;
    for (int j = tid; j < LRES; j += 256) {
        float dx = cax - X[((size_t)j * 37 + 1) * 3 + 0];
        float dy = cay - X[((size_t)j * 37 + 1) * 3 + 1];
        float dz = caz - X[((size_t)j * 37 + 1) * 3 + 2];
        float s = dx * dx + dy * dy + dz * dz;
        float m2 = mi * mask[j];
        float Dv = m2 * sqrtf(s + 1e-6f);
        dsh[j] = Dv;
        lmax = fmaxf(lmax, Dv);
    }
    for (int off = 16; off; off >>= 1)
        lmax = fmaxf(lmax, __shfl_xor_sync(0xffffffffu, lmax, off));
    if ((tid & 31) == 0) wmaxs[tid >> 5] = lmax;
    __syncthreads();
    if (tid == 0) {
        float m = wmaxs[0];
        #pragma unroll
        for (int w = 1; w < 8; w++) m = fmaxf(m, wmaxs[w]);
        smDmax = m;
    }
    __syncthreads();
    float Dmax = smDmax;

    for (int j = tid; j < LRES; j += 256) {
        float m2 = mi * mask[j];
        float Dadj = dsh[j] + (1.0f - m2) * Dmax;
        keys[j] = (((unsigned long long)__float_as_uint(Dadj)) << 32) |
                  (unsigned int)j;
    }
    __syncthreads();

    for (int sel = 0; sel < TOPK; sel++) {
        unsigned long long lmin = 0xffffffffffffffffull;
        #pragma unroll
        for (int c = 0; c < 4; c++) lmin = u64min_(lmin, keys[tid + 256 * c]);
        for (int off = 16; off; off >>= 1) {
            unsigned long long o2 = __shfl_xor_sync(0xffffffffu, lmin, off);
            lmin = u64min_(lmin, o2);
        }
        if ((tid & 31) == 0) wmins[tid >> 5] = lmin;
        __syncthreads();
        if (tid == 0) {
            unsigned long long m = wmins[0];
            #pragma unroll
            for (int w = 1; w < 8; w++) m = u64min_(m, wmins[w]);
            int j = (int)(m & 0xffffffffull);
            float dv = __uint_as_float((unsigned int)(m >> 32));
            g_eidx[i * TOPK + sel] = j;
            g_dnb[i * TOPK + sel] = dv;
            out[OFF_EIDX + (size_t)i * TOPK + sel] = (float)j;
            out[OFF_EIDXSUB + (size_t)i * TOPK + sel] = (float)j;
            keys[j] = 0xffffffffffffffffull;
        }
        __syncthreads();
    }
}

// ---------------------------------------------------------------------------
// Kernel 3: E. 256 threads, warp = (edge-group[4] x 12 edges, channel-half[2]).
// Thread owns 2 adjacent channels; edges warp-uniform (broadcast feat loads).
// ---------------------------------------------------------------------------
__global__ void __launch_bounds__(256, 2) e_kernel(
    const float* __restrict__ Wpos, const float* __restrict__ bpos,
    const int* __restrict__ ridx, const int* __restrict__ clab,
    const float* __restrict__ We, const float* __restrict__ ge,
    const float* __restrict__ be, float* __restrict__ out) {
    extern __shared__ float feats[];  // 48*416 floats, then Wsm2 16*130 ull
    unsigned long long* Wsm2 = (unsigned long long*)(feats + TOPK * EF);
    int i = blockIdx.x;
    int tid = threadIdx.x;
    int wid = tid >> 5, lane = tid & 31;

    if (tid < TOPK) {
        int k = tid;
        int j = g_eidx[i * TOPK + k];
        int offr = ridx[i] - ridx[j];
        int ec = (clab[i] == clab[j]) ? 1 : 0;
        int d = min(max(offr + 32, 0), 64) * ec + (1 - ec) * 65;
        float* fr = feats + k * EF;
        #pragma unroll
        for (int f = 0; f < 16; f++) fr[f] = Wpos[f * 66 + d] + bpos[f];
        rbf_gen<16>(g_dnb[i * TOPK + k], 1.0f, fr + 16, E_SINV, E_D2, E_E2);
    }

    const signed char pa[24] = {0,2,3,4,1,1,1,1,0,0,0,4,4,3,0,2,3,4,2,3,4,2,3,2};
    const signed char pb[24] = {0,2,3,4,0,2,3,4,2,3,4,2,3,2,1,1,1,1,0,0,0,4,4,3};
    for (int tt = tid; tt < TOPK * 24; tt += 256) {
        int k = tt / 24, p = tt - k * 24;
        int j = g_eidx[i * TOPK + k];
        const float* A = g_coords + i * 15 + (int)pa[p] * 3;
        const float* B = g_coords + j * 15 + (int)pb[p] * 3;
        float dx = A[0] - B[0], dy = A[1] - B[1], dz = A[2] - B[2];
        float D = sqrtf(dx * dx + dy * dy + dz * dz + 1e-6f);
        rbf_gen<16>(D, 1.0f, feats + k * EF + 32 + p * 16, E_SINV, E_D2, E_E2);
    }

    int eg = wid >> 1;        // 4 edge groups x 12 edges
    int chh = wid & 1;        // channel half
    int op = chh * 64 + 2 * lane;   // W pair index (channels op, op+1)
    unsigned long long acc0[12], acc1[12];
    #pragma unroll
    for (int k = 0; k < 12; k++) { acc0[k] = 0ull; acc1[k] = 0ull; }

    for (int st = 0; st < EF / 32; st++) {
        __syncthreads();
        stage_w(We, EF, st * 32, Wsm2, tid);
        __syncthreads();
        const float* fb = feats + st * 32;
        #pragma unroll
        for (int q = 0; q < 8; q++) {
            ulonglong2 wa = *(const ulonglong2*)(Wsm2 + (2 * q) * 130 + op);
            ulonglong2 wb = *(const ulonglong2*)(Wsm2 + (2 * q + 1) * 130 + op);
            #pragma unroll
            for (int k = 0; k < 12; k++) {
                ulonglong2 v = *(const ulonglong2*)(fb + (eg * 12 + k) * EF + 4 * q);
                acc0[k] = fma2(wa.x, v.x, acc0[k]);
                acc0[k] = fma2(wb.x, v.y, acc0[k]);
                acc1[k] = fma2(wa.y, v.x, acc1[k]);
                acc1[k] = fma2(wb.y, v.y, acc1[k]);
            }
        }
    }
    __syncthreads();

    float* h = feats;  // 48*128
    #pragma unroll
    for (int k = 0; k < 12; k++) {
        h[(eg * 12 + k) * 128 + op] = pairsum(acc0[k]);
        h[(eg * 12 + k) * 128 + op + 1] = pairsum(acc1[k]);
    }
    __syncthreads();

    for (int k = wid; k < TOPK; k += 8) {
        float v0 = h[k * 128 + lane];
        float v1 = h[k * 128 + lane + 32];
        float v2 = h[k * 128 + lane + 64];
        float v3 = h[k * 128 + lane + 96];
        float s = v0 + v1 + v2 + v3;
        for (int off = 16; off; off >>= 1) s += __shfl_xor_sync(0xffffffffu, s, off);
        float mu = s * (1.0f / 128.0f);
        float d0 = v0 - mu, d1 = v1 - mu, d2 = v2 - mu, d3 = v3 - mu;
        float s2 = d0 * d0 + d1 * d1 + d2 * d2 + d3 * d3;
        for (int off = 16; off; off >>= 1) s2 += __shfl_xor_sync(0xffffffffu, s2, off);
        float inv = rsqrtf(s2 * (1.0f / 128.0f) + 1e-5f);
        size_t base = OFF_E + ((size_t)(i * TOPK + k)) * 128;
        out[base + lane]      = ge[lane]      * d0 * inv + be[lane];
        out[base + lane + 32] = ge[lane + 32] * d1 * inv + be[lane + 32];
        out[base + lane + 64] = ge[lane + 64] * d2 * inv + be[lane + 64];
        out[base + lane + 96] = ge[lane + 96] * d3 * inv + be[lane + 96];
    }
}

// ---------------------------------------------------------------------------
// Kernel 4: E_s. 256 threads, warp = (edge-group[2] x 8, ch-half[2], feat-half[2]).
// ---------------------------------------------------------------------------
__global__ void __launch_bounds__(256, 2) es_kernel(
    const float* __restrict__ X, const float* __restrict__ amask,
    const float* __restrict__ Ws, const float* __restrict__ gs,
    const float* __restrict__ bs, float* __restrict__ out) {
    extern __shared__ float feats[];  // 16*1280 floats, then Wsm2 16*130 ull
    unsigned long long* Wsm2 = (unsigned long long*)(feats + KT * SF);
    __shared__ int jn[KT];
    __shared__ float anch[15];

    int bx = blockIdx.x;
    int i = bx / NTILE;
    int k0 = (bx - i * NTILE) * KT;
    int tid = threadIdx.x;
    int wid = tid >> 5, lane = tid & 31;

    if (tid < KT) jn[tid] = g_eidx[i * TOPK + k0 + tid];
    if (tid >= 32 && tid < 47) anch[tid - 32] = g_coords[i * 15 + (tid - 32)];
    __syncthreads();

    for (int tt = tid; tt < KT * 160; tt += 256) {
        int kk = tt / 160;
        int rem = tt - kk * 160;
        int a = rem >> 5, s = rem & 31;
        int j = jn[kk];
        const float* Sp = X + ((size_t)j * 37 + 5 + s) * 3;
        float dx = anch[a * 3 + 0] - Sp[0];
        float dy = anch[a * 3 + 1] - Sp[1];
        float dz = anch[a * 3 + 2] - Sp[2];
        float D = sqrtf(dx * dx + dy * dy + dz * dz + 1e-6f);
        float m = amask[(size_t)j * 37 + 5 + s];
        rbf_gen<8>(D, m, feats + kk * SF + (a * 32 + s) * 8, S_SINV, S_D2, S_E2);
    }

    int eg = wid >> 2;         // 2 edge groups x 8 edges
    int chh = (wid >> 1) & 1;  // channel half
    int fh = wid & 1;          // feature half of each 32-feat stage
    int op = chh * 64 + 2 * lane;
    unsigned long long acc0[8], acc1[8];
    #pragma unroll
    for (int k = 0; k < 8; k++) { acc0[k] = 0ull; acc1[k] = 0ull; }

    for (int st = 0; st < SF / 32; st++) {
        __syncthreads();
        stage_w(Ws, SF, st * 32, Wsm2, tid);
        __syncthreads();
        const float* fb = feats + st * 32 + fh * 16;
        #pragma unroll
        for (int q = 0; q < 4; q++) {
            int f2a = fh * 8 + 2 * q;
            ulonglong2 wa = *(const ulonglong2*)(Wsm2 + f2a * 130 + op);
            ulonglong2 wb = *(const ulonglong2*)(Wsm2 + (f2a + 1) * 130 + op);
            #pragma unroll
            for (int k = 0; k < 8; k++) {
                ulonglong2 v = *(const ulonglong2*)(fb + (eg * 8 + k) * SF + 4 * q);
                acc0[k] = fma2(wa.x, v.x, acc0[k]);
                acc0[k] = fma2(wb.x, v.y, acc0[k]);
                acc1[k] = fma2(wa.y, v.x, acc1[k]);
                acc1[k] = fma2(wb.y, v.y, acc1[k]);
            }
        }
    }
    __syncthreads();

    float* h = feats;  // 16*128
    if (fh == 0) {
        #pragma unroll
        for (int k = 0; k < 8; k++) {
            h[(eg * 8 + k) * 128 + op] = pairsum(acc0[k]);
            h[(eg * 8 + k) * 128 + op + 1] = pairsum(acc1[k]);
        }
    }
    __syncthreads();
    if (fh == 1) {
        #pragma unroll
        for (int k = 0; k < 8; k++) {
            h[(eg * 8 + k) * 128 + op] += pairsum(acc0[k]);
            h[(eg * 8 + k) * 128 + op + 1] += pairsum(acc1[k]);
        }
    }
    __syncthreads();

    for (int kk = wid; kk < KT; kk += 8) {
        float v0 = h[kk * 128 + lane];
        float v1 = h[kk * 128 + lane + 32];
        float v2 = h[kk * 128 + lane + 64];
        float v3 = h[kk * 128 + lane + 96];
        float s = v0 + v1 + v2 + v3;
        for (int off = 16; off; off >>= 1) s += __shfl_xor_sync(0xffffffffu, s, off);
        float mu = s * (1.0f / 128.0f);
        float d0 = v0 - mu, d1 = v1 - mu, d2 = v2 - mu, d3 = v3 - mu;
        float s2 = d0 * d0 + d1 * d1 + d2 * d2 + d3 * d3;
        for (int off = 16; off; off >>= 1) s2 += __shfl_xor_sync(0xffffffffu, s2, off);
        float inv = rsqrtf(s2 * (1.0f / 128.0f) + 1e-5f);
        size_t base = OFF_ES + ((size_t)(i * TOPK + k0 + kk)) * 128;
        out[base + lane]      = gs[lane]      * d0 * inv + bs[lane];
        out[base + lane + 32] = gs[lane + 32] * d1 * inv + bs[lane + 32];
        out[base + lane + 64] = gs[lane + 64] * d2 * inv + bs[lane + 64];
        out[base + lane + 96] = gs[lane + 96] * d3 * inv + bs[lane + 96];
    }
}

// ---------------------------------------------------------------------------
extern "C" void kernel_launch(void* const* d_in, const int* in_sizes, int n_in,
                              void* d_out, int out_size) {
    (void)in_sizes; (void)n_in; (void)out_size;
    const float* X     = (const float*)d_in[0];
    const float* mask  = (const float*)d_in[2];
    const float* amask = (const float*)d_in[3];
    const int*   ridx  = (const int*)d_in[4];
    const int*   clab  = (const int*)d_in[6];
    const float* Wpos  = (const float*)d_in[7];
    const float* bpos  = (const float*)d_in[8];
    const float* We    = (const float*)d_in[9];
    const float* ge    = (const float*)d_in[10];
    const float* be    = (const float*)d_in[11];
    const float* Ws    = (const float*)d_in[12];
    const float* gs    = (const float*)d_in[13];
    const float* bs    = (const float*)d_in[14];
    float* out = (float*)d_out;

    int e_smem  = TOPK * EF * 4 + 16 * 130 * 8;   // 96512
    int es_smem = KT * SF * 4 + 16 * 130 * 8;     // 98560
    cudaFuncSetAttribute(e_kernel, cudaFuncAttributeMaxDynamicSharedMemorySize,
                         e_smem);
    cudaFuncSetAttribute(es_kernel, cudaFuncAttributeMaxDynamicSharedMemorySize,
                         es_smem);

    geom_kernel<<<(LRES + 255) / 256, 256>>>(X);
    topk_kernel<<<LRES, 256>>>(X, mask, out);
    e_kernel<<<LRES, 256, e_smem>>>(Wpos, bpos, ridx, clab, We, ge, be, out);
    es_kernel<<<LRES * NTILE, 256, es_smem>>>(X, amask, Ws, gs, bs, out);
}